// round 1
// baseline (speedup 1.0000x reference)
#include <cuda_runtime.h>
#include <cstdint>

#define BB 8
#define TT 2048
#define CC 1024
#define HH 128

// Scratch for Q, K, V projections (fp32, [B*T, H])
__device__ float g_Q[BB*TT*HH];
__device__ float g_K[BB*TT*HH];
__device__ float g_V[BB*TT*HH];

// ------------------------------------------------------------------
// Stage 1: QKV projection GEMM.  out[M,128] = X[M,1024] * W[1024,128]
// M = B*T = 16384.  Block tile 128x128, BK=16, 256 threads, 8x8/thread.
// ------------------------------------------------------------------
#define GBM 128
#define GBK 16
#define ASTR 132
#define BSTR 132

__global__ __launch_bounds__(256) void qkv_gemm_kernel(
    const float* __restrict__ X,
    const float* __restrict__ Wk,
    const float* __restrict__ Wq,
    const float* __restrict__ Wv)
{
    const float* __restrict__ W;
    float* __restrict__ out;
    switch (blockIdx.y) {
        case 0:  W = Wk; out = g_K; break;
        case 1:  W = Wq; out = g_Q; break;
        default: W = Wv; out = g_V; break;
    }

    __shared__ float As[GBK * ASTR];   // transposed: As[k][m]
    __shared__ float Bs[GBK * BSTR];   // Bs[k][n]

    const int t  = threadIdx.x;
    const int tx = t & 15;             // n-dir
    const int ty = t >> 4;             // m-dir
    const int row0 = blockIdx.x * GBM;

    float acc[8][8];
    #pragma unroll
    for (int i = 0; i < 8; ++i)
        #pragma unroll
        for (int j = 0; j < 8; ++j) acc[i][j] = 0.f;

    for (int k0 = 0; k0 < CC; k0 += GBK) {
        // Load X tile (128 rows x 16 k), store transposed into As
        #pragma unroll
        for (int r = 0; r < 2; ++r) {
            int idx = t + r * 256;           // 0..511 float4s
            int rr  = idx >> 2;              // row 0..127
            int kc  = (idx & 3) << 2;        // k chunk 0,4,8,12
            float4 v = *(const float4*)&X[(size_t)(row0 + rr) * CC + k0 + kc];
            As[(kc + 0) * ASTR + rr] = v.x;
            As[(kc + 1) * ASTR + rr] = v.y;
            As[(kc + 2) * ASTR + rr] = v.z;
            As[(kc + 3) * ASTR + rr] = v.w;
        }
        // Load W tile (16 rows x 128 n)
        #pragma unroll
        for (int r = 0; r < 2; ++r) {
            int idx = t + r * 256;           // 0..511 float4s
            int rr  = idx >> 5;              // k row 0..15
            int c4  = (idx & 31) << 2;       // n col
            *(float4*)&Bs[rr * BSTR + c4] =
                *(const float4*)&W[(size_t)(k0 + rr) * HH + c4];
        }
        __syncthreads();

        #pragma unroll
        for (int kk = 0; kk < GBK; ++kk) {
            float4 a0 = *(float4*)&As[kk * ASTR + (ty << 2)];
            float4 a1 = *(float4*)&As[kk * ASTR + 64 + (ty << 2)];
            float4 b0 = *(float4*)&Bs[kk * BSTR + (tx << 2)];
            float4 b1 = *(float4*)&Bs[kk * BSTR + 64 + (tx << 2)];
            float am[8] = {a0.x, a0.y, a0.z, a0.w, a1.x, a1.y, a1.z, a1.w};
            float bn[8] = {b0.x, b0.y, b0.z, b0.w, b1.x, b1.y, b1.z, b1.w};
            #pragma unroll
            for (int mi = 0; mi < 8; ++mi)
                #pragma unroll
                for (int ni = 0; ni < 8; ++ni)
                    acc[mi][ni] += am[mi] * bn[ni];
        }
        __syncthreads();
    }

    // Epilogue
    #pragma unroll
    for (int mi = 0; mi < 8; ++mi) {
        int rr = row0 + ((mi < 4) ? ((ty << 2) + mi) : (64 + (ty << 2) + mi - 4));
        float4 o0 = make_float4(acc[mi][0], acc[mi][1], acc[mi][2], acc[mi][3]);
        float4 o1 = make_float4(acc[mi][4], acc[mi][5], acc[mi][6], acc[mi][7]);
        *(float4*)&out[(size_t)rr * HH + (tx << 2)]      = o0;
        *(float4*)&out[(size_t)rr * HH + 64 + (tx << 2)] = o1;
    }
}

// ------------------------------------------------------------------
// Stage 2: causal flash attention, fp32.
// Block = (qtile, b): BQ=64 query rows.  Key tiles BK=64.
// Q/K/V tiles in XOR-swizzled smem (conflict-free float4).
// S (64x64) in smem; O accumulator in registers (float4[8]/thread).
// ------------------------------------------------------------------
#define BQ 64
#define BKT 64
#define SSTR 65

// floats: Qs 8192 + Ks 8192 + Vs 8192 + Ss 64*65 + m/l/alpha 192
#define ATTN_SMEM_FLOATS (3 * 8192 + BQ * SSTR + 192)
#define ATTN_SMEM_BYTES  (ATTN_SMEM_FLOATS * 4)

__global__ __launch_bounds__(256) void attn_kernel(float* __restrict__ out)
{
    extern __shared__ float sm[];
    float* Qs   = sm;                 // [64][128] swizzled
    float* Ks   = sm + 8192;
    float* Vs   = sm + 16384;
    float* Ss   = sm + 24576;         // [64][65]
    float* m_s  = Ss + BQ * SSTR;     // [64]
    float* l_s  = m_s + 64;
    float* al_s = l_s + 64;

    const int t  = threadIdx.x;
    const int b  = blockIdx.y;
    const int qt = (int)gridDim.x - 1 - (int)blockIdx.x;   // LPT order
    const int q0 = qt * BQ;
    const float scale = 0.08838834764831845f;              // 1/sqrt(128)

    // Load Q tile (scale folded in), swizzled layout
    #pragma unroll
    for (int r = 0; r < 8; ++r) {
        int idx = t + r * 256;         // 0..2047 float4s
        int i   = idx >> 5;            // row 0..63
        int hc  = idx & 31;            // chunk 0..31
        float4 v = *(const float4*)&g_Q[((size_t)(b * TT + q0 + i)) * HH + (hc << 2)];
        v.x *= scale; v.y *= scale; v.z *= scale; v.w *= scale;
        *(float4*)&Qs[i * 128 + ((hc ^ (i & 31)) << 2)] = v;
    }
    if (t < 64) { m_s[t] = -1e30f; l_s[t] = 0.f; }

    float4 acc[8];
    #pragma unroll
    for (int e = 0; e < 8; ++e) acc[e] = make_float4(0.f, 0.f, 0.f, 0.f);

    const int tx = t & 15;             // S-phase: j dir
    const int ty = t >> 4;             // S-phase: i dir
    const int hc = t & 31;             // PV: col chunk
    const int w  = t >> 5;             // PV: row offset (warp id)

    __syncthreads();

    for (int kt = 0; kt <= qt; ++kt) {
        const int s0 = kt * BKT;
        // Load K, V tiles (swizzled)
        #pragma unroll
        for (int r = 0; r < 8; ++r) {
            int idx = t + r * 256;
            int j   = idx >> 5;
            int c   = idx & 31;
            size_t base = ((size_t)(b * TT + s0 + j)) * HH + (c << 2);
            int soff = j * 128 + ((c ^ (j & 31)) << 2);
            *(float4*)&Ks[soff] = *(const float4*)&g_K[base];
            *(float4*)&Vs[soff] = *(const float4*)&g_V[base];
        }
        __syncthreads();

        // S = Q K^T  (scale already folded into Q)
        float s[4][4];
        #pragma unroll
        for (int r = 0; r < 4; ++r)
            #pragma unroll
            for (int c = 0; c < 4; ++c) s[r][c] = 0.f;

        #pragma unroll 8
        for (int kc = 0; kc < 32; ++kc) {
            float4 q4[4], k4[4];
            #pragma unroll
            for (int r = 0; r < 4; ++r) {
                int i = (ty << 2) + r;
                q4[r] = *(float4*)&Qs[i * 128 + ((kc ^ (i & 31)) << 2)];
            }
            #pragma unroll
            for (int c = 0; c < 4; ++c) {
                int j = (tx << 2) + c;
                k4[c] = *(float4*)&Ks[j * 128 + ((kc ^ (j & 31)) << 2)];
            }
            #pragma unroll
            for (int r = 0; r < 4; ++r)
                #pragma unroll
                for (int c = 0; c < 4; ++c) {
                    s[r][c] += q4[r].x * k4[c].x;
                    s[r][c] += q4[r].y * k4[c].y;
                    s[r][c] += q4[r].z * k4[c].z;
                    s[r][c] += q4[r].w * k4[c].w;
                }
        }

        const bool diag = (kt == qt);
        #pragma unroll
        for (int r = 0; r < 4; ++r)
            #pragma unroll
            for (int c = 0; c < 4; ++c) {
                int i = (ty << 2) + r, j = (tx << 2) + c;
                Ss[i * SSTR + j] = (diag && (j > i)) ? -1e30f : s[r][c];
            }
        __syncthreads();

        // Online softmax update (4 threads per row, 16 cols each)
        {
            int row = t >> 2, seg = t & 3;
            float* srow = &Ss[row * SSTR + seg * 16];
            float mloc = -1e30f;
            #pragma unroll
            for (int jj = 0; jj < 16; ++jj) mloc = fmaxf(mloc, srow[jj]);
            mloc = fmaxf(mloc, __shfl_xor_sync(0xffffffffu, mloc, 1));
            mloc = fmaxf(mloc, __shfl_xor_sync(0xffffffffu, mloc, 2));
            float mold = m_s[row];
            float mnew = fmaxf(mold, mloc);
            float lsum = 0.f;
            #pragma unroll
            for (int jj = 0; jj < 16; ++jj) {
                float p = __expf(srow[jj] - mnew);
                srow[jj] = p;
                lsum += p;
            }
            lsum += __shfl_xor_sync(0xffffffffu, lsum, 1);
            lsum += __shfl_xor_sync(0xffffffffu, lsum, 2);
            if (seg == 0) {
                float a = __expf(mold - mnew);
                al_s[row] = a;
                m_s[row]  = mnew;
                l_s[row]  = l_s[row] * a + lsum;
            }
        }
        __syncthreads();

        // Rescale O, then O += P * V
        #pragma unroll
        for (int e = 0; e < 8; ++e) {
            float a = al_s[(e << 3) + w];
            acc[e].x *= a; acc[e].y *= a; acc[e].z *= a; acc[e].w *= a;
        }
        #pragma unroll 4
        for (int j = 0; j < BKT; ++j) {
            float4 v4 = *(float4*)&Vs[j * 128 + ((hc ^ (j & 31)) << 2)];
            #pragma unroll
            for (int e = 0; e < 8; ++e) {
                float p = Ss[((e << 3) + w) * SSTR + j];
                acc[e].x += p * v4.x;
                acc[e].y += p * v4.y;
                acc[e].z += p * v4.z;
                acc[e].w += p * v4.w;
            }
        }
        __syncthreads();
    }

    // Final normalize + write
    #pragma unroll
    for (int e = 0; e < 8; ++e) {
        int i = (e << 3) + w;
        float invl = 1.0f / l_s[i];
        float4 o = make_float4(acc[e].x * invl, acc[e].y * invl,
                               acc[e].z * invl, acc[e].w * invl);
        *(float4*)&out[((size_t)(b * TT + q0 + i)) * HH + (hc << 2)] = o;
    }
}

// ------------------------------------------------------------------
extern "C" void kernel_launch(void* const* d_in, const int* in_sizes, int n_in,
                              void* d_out, int out_size)
{
    const float* x  = (const float*)d_in[0];
    const float* Wk = (const float*)d_in[1];
    const float* Wq = (const float*)d_in[2];
    const float* Wv = (const float*)d_in[3];
    float* out = (float*)d_out;

    (void)in_sizes; (void)n_in; (void)out_size;

    cudaFuncSetAttribute(attn_kernel,
                         cudaFuncAttributeMaxDynamicSharedMemorySize,
                         ATTN_SMEM_BYTES);

    qkv_gemm_kernel<<<dim3(BB * TT / GBM, 3), 256>>>(x, Wk, Wq, Wv);
    attn_kernel<<<dim3(TT / BQ, BB), 256, ATTN_SMEM_BYTES>>>(out);
}

// round 2
// speedup vs baseline: 1.5431x; 1.5431x over previous
#include <cuda_runtime.h>
#include <cstdint>

#define BB 8
#define TT 2048
#define CC 1024
#define HH 128

// Scratch for Q, K, V projections (fp32, [B*T, H])
__device__ float g_Q[BB*TT*HH];
__device__ float g_K[BB*TT*HH];
__device__ float g_V[BB*TT*HH];

// ------------------------------------------------------------------
// Stage 1: QKV projection GEMM.  out[M,128] = X[M,1024] * W[1024,128]
// (unchanged from R1: ~35 TF/s, at fp32 FFMA roofline)
// ------------------------------------------------------------------
#define GBM 128
#define GBK 16
#define ASTR 132
#define BSTR 132

__global__ __launch_bounds__(256) void qkv_gemm_kernel(
    const float* __restrict__ X,
    const float* __restrict__ Wk,
    const float* __restrict__ Wq,
    const float* __restrict__ Wv)
{
    const float* __restrict__ W;
    float* __restrict__ out;
    switch (blockIdx.y) {
        case 0:  W = Wk; out = g_K; break;
        case 1:  W = Wq; out = g_Q; break;
        default: W = Wv; out = g_V; break;
    }

    __shared__ float As[GBK * ASTR];   // transposed: As[k][m]
    __shared__ float Bs[GBK * BSTR];   // Bs[k][n]

    const int t  = threadIdx.x;
    const int tx = t & 15;             // n-dir
    const int ty = t >> 4;             // m-dir
    const int row0 = blockIdx.x * GBM;

    float acc[8][8];
    #pragma unroll
    for (int i = 0; i < 8; ++i)
        #pragma unroll
        for (int j = 0; j < 8; ++j) acc[i][j] = 0.f;

    for (int k0 = 0; k0 < CC; k0 += GBK) {
        #pragma unroll
        for (int r = 0; r < 2; ++r) {
            int idx = t + r * 256;
            int rr  = idx >> 2;
            int kc  = (idx & 3) << 2;
            float4 v = *(const float4*)&X[(size_t)(row0 + rr) * CC + k0 + kc];
            As[(kc + 0) * ASTR + rr] = v.x;
            As[(kc + 1) * ASTR + rr] = v.y;
            As[(kc + 2) * ASTR + rr] = v.z;
            As[(kc + 3) * ASTR + rr] = v.w;
        }
        #pragma unroll
        for (int r = 0; r < 2; ++r) {
            int idx = t + r * 256;
            int rr  = idx >> 5;
            int c4  = (idx & 31) << 2;
            *(float4*)&Bs[rr * BSTR + c4] =
                *(const float4*)&W[(size_t)(k0 + rr) * HH + c4];
        }
        __syncthreads();

        #pragma unroll
        for (int kk = 0; kk < GBK; ++kk) {
            float4 a0 = *(float4*)&As[kk * ASTR + (ty << 2)];
            float4 a1 = *(float4*)&As[kk * ASTR + 64 + (ty << 2)];
            float4 b0 = *(float4*)&Bs[kk * BSTR + (tx << 2)];
            float4 b1 = *(float4*)&Bs[kk * BSTR + 64 + (tx << 2)];
            float am[8] = {a0.x, a0.y, a0.z, a0.w, a1.x, a1.y, a1.z, a1.w};
            float bn[8] = {b0.x, b0.y, b0.z, b0.w, b1.x, b1.y, b1.z, b1.w};
            #pragma unroll
            for (int mi = 0; mi < 8; ++mi)
                #pragma unroll
                for (int ni = 0; ni < 8; ++ni)
                    acc[mi][ni] += am[mi] * bn[ni];
        }
        __syncthreads();
    }

    #pragma unroll
    for (int mi = 0; mi < 8; ++mi) {
        int rr = row0 + ((mi < 4) ? ((ty << 2) + mi) : (64 + (ty << 2) + mi - 4));
        float4 o0 = make_float4(acc[mi][0], acc[mi][1], acc[mi][2], acc[mi][3]);
        float4 o1 = make_float4(acc[mi][4], acc[mi][5], acc[mi][6], acc[mi][7]);
        *(float4*)&out[(size_t)rr * HH + (tx << 2)]      = o0;
        *(float4*)&out[(size_t)rr * HH + 64 + (tx << 2)] = o1;
    }
}

// ------------------------------------------------------------------
// Stage 2 (v2): causal flash attention, fp32.
// 128 threads/block, BQ=64, BKT=64.
//   S-phase : thread grid 8x16 (ti,tj), 8 rows x 4 cols per thread
//   softmax : fully in registers; shfl reduce over 16 lanes per row;
//             m,l replicated in registers (deterministic -> consistent)
//   P       : written TRANSPOSED to smem -> PV reads P as broadcast float4
//   PV-phase: thread owns O[8 rows x 8 cols]; 4 LDS128 per 64 FMA
// Global LPT work order: qt = 31 - bid/8, batch fastest.
// ------------------------------------------------------------------
#define BQ 64
#define BKT 64
#define PSTR 68     // Pt row stride (floats): (4*tj*17)%32 distinct per phase

// floats: Qs 8192 + Ks 8192 + Vs 8192 + Pt 64*68
#define ATTN_SMEM_FLOATS (3 * 8192 + BKT * PSTR)
#define ATTN_SMEM_BYTES  (ATTN_SMEM_FLOATS * 4)

__device__ __forceinline__ int qswz(int row, int chunk) {
    // 16B-chunk XOR swizzle inside a 128-float row
    return row * 128 + ((chunk ^ (row & 31)) << 2);
}

__global__ __launch_bounds__(128) void attn_kernel(float* __restrict__ out)
{
    extern __shared__ float sm[];
    float* Qs = sm;                  // [64][128] swizzled
    float* Ks = sm + 8192;           // [64][128] swizzled
    float* Vs = sm + 16384;          // [64][128] plain
    float* Pt = sm + 24576;          // [64][PSTR]  Pt[j][i]

    const int t   = threadIdx.x;
    const int tj  = t & 15;          // 0..15  (S cols / O col-chunk)
    const int ti  = t >> 4;          // 0..7   (S rows / O rows)
    const int bid = blockIdx.x;
    const int b   = bid & 7;
    const int qt  = 31 - (bid >> 3); // global LPT: big tiles first
    const int q0  = qt * BQ;
    const float scale = 0.08838834764831845f;   // 1/sqrt(128)

    // ---- load Q tile (scale folded), swizzled ----
    #pragma unroll
    for (int r = 0; r < 16; ++r) {
        int idx = t + r * 128;       // 0..2047 float4s
        int i   = idx >> 5;
        int c   = idx & 31;
        float4 v = *(const float4*)&g_Q[((size_t)(b * TT + q0 + i)) * HH + (c << 2)];
        v.x *= scale; v.y *= scale; v.z *= scale; v.w *= scale;
        *(float4*)&Qs[qswz(i, c)] = v;
    }

    float4 acc[8][2];                // O[8 rows][8 cols]
    #pragma unroll
    for (int r = 0; r < 8; ++r) {
        acc[r][0] = make_float4(0.f,0.f,0.f,0.f);
        acc[r][1] = make_float4(0.f,0.f,0.f,0.f);
    }
    float m_r[8], l_r[8];
    #pragma unroll
    for (int r = 0; r < 8; ++r) { m_r[r] = -1e30f; l_r[r] = 0.f; }

    __syncthreads();

    for (int kt = 0; kt <= qt; ++kt) {
        const int s0 = kt * BKT;
        // ---- load K (swizzled), V (plain) ----
        #pragma unroll
        for (int r = 0; r < 16; ++r) {
            int idx = t + r * 128;
            int j   = idx >> 5;
            int c   = idx & 31;
            size_t base = ((size_t)(b * TT + s0 + j)) * HH + (c << 2);
            *(float4*)&Ks[qswz(j, c)]    = *(const float4*)&g_K[base];
            *(float4*)&Vs[j * 128 + (c << 2)] = *(const float4*)&g_V[base];
        }
        __syncthreads();

        // ---- S = Q K^T  (8x4 per thread) ----
        float s[8][4];
        #pragma unroll
        for (int r = 0; r < 8; ++r)
            #pragma unroll
            for (int c = 0; c < 4; ++c) s[r][c] = 0.f;

        #pragma unroll 4
        for (int kc = 0; kc < 32; ++kc) {
            float4 k4[4];
            #pragma unroll
            for (int c = 0; c < 4; ++c)
                k4[c] = *(float4*)&Ks[qswz((tj << 2) + c, kc)];
            #pragma unroll
            for (int r = 0; r < 8; ++r) {
                float4 q4 = *(float4*)&Qs[qswz((ti << 3) + r, kc)];
                #pragma unroll
                for (int c = 0; c < 4; ++c) {
                    s[r][c] += q4.x * k4[c].x;
                    s[r][c] += q4.y * k4[c].y;
                    s[r][c] += q4.z * k4[c].z;
                    s[r][c] += q4.w * k4[c].w;
                }
            }
        }

        // ---- causal mask on diagonal tile ----
        if (kt == qt) {
            #pragma unroll
            for (int r = 0; r < 8; ++r) {
                int i = (ti << 3) + r;
                #pragma unroll
                for (int c = 0; c < 4; ++c)
                    if (((tj << 2) + c) > i) s[r][c] = -1e30f;
            }
        }

        // ---- online softmax in registers ----
        float alpha[8];
        #pragma unroll
        for (int r = 0; r < 8; ++r) {
            float ml = fmaxf(fmaxf(s[r][0], s[r][1]), fmaxf(s[r][2], s[r][3]));
            ml = fmaxf(ml, __shfl_xor_sync(0xffffffffu, ml, 1));
            ml = fmaxf(ml, __shfl_xor_sync(0xffffffffu, ml, 2));
            ml = fmaxf(ml, __shfl_xor_sync(0xffffffffu, ml, 4));
            ml = fmaxf(ml, __shfl_xor_sync(0xffffffffu, ml, 8));
            float mnew = fmaxf(m_r[r], ml);
            alpha[r] = __expf(m_r[r] - mnew);
            m_r[r]   = mnew;
            float ls = 0.f;
            #pragma unroll
            for (int c = 0; c < 4; ++c) {
                float p = __expf(s[r][c] - mnew);
                s[r][c] = p;
                ls += p;
            }
            ls += __shfl_xor_sync(0xffffffffu, ls, 1);
            ls += __shfl_xor_sync(0xffffffffu, ls, 2);
            ls += __shfl_xor_sync(0xffffffffu, ls, 4);
            ls += __shfl_xor_sync(0xffffffffu, ls, 8);
            l_r[r] = l_r[r] * alpha[r] + ls;
        }

        // ---- write P transposed: Pt[j][i] ----
        #pragma unroll
        for (int c = 0; c < 4; ++c) {
            int j = (tj << 2) + c;
            *(float4*)&Pt[j * PSTR + (ti << 3)] =
                make_float4(s[0][c], s[1][c], s[2][c], s[3][c]);
            *(float4*)&Pt[j * PSTR + (ti << 3) + 4] =
                make_float4(s[4][c], s[5][c], s[6][c], s[7][c]);
        }
        __syncthreads();

        // ---- rescale O, then O += P V ----
        #pragma unroll
        for (int r = 0; r < 8; ++r) {
            float a = alpha[r];
            acc[r][0].x *= a; acc[r][0].y *= a; acc[r][0].z *= a; acc[r][0].w *= a;
            acc[r][1].x *= a; acc[r][1].y *= a; acc[r][1].z *= a; acc[r][1].w *= a;
        }
        #pragma unroll 4
        for (int j = 0; j < BKT; ++j) {
            float4 v0 = *(float4*)&Vs[j * 128 + (tj << 3)];
            float4 v1 = *(float4*)&Vs[j * 128 + (tj << 3) + 4];
            float4 pa = *(float4*)&Pt[j * PSTR + (ti << 3)];
            float4 pb = *(float4*)&Pt[j * PSTR + (ti << 3) + 4];
            float pr[8] = {pa.x, pa.y, pa.z, pa.w, pb.x, pb.y, pb.z, pb.w};
            #pragma unroll
            for (int r = 0; r < 8; ++r) {
                acc[r][0].x += pr[r] * v0.x;
                acc[r][0].y += pr[r] * v0.y;
                acc[r][0].z += pr[r] * v0.z;
                acc[r][0].w += pr[r] * v0.w;
                acc[r][1].x += pr[r] * v1.x;
                acc[r][1].y += pr[r] * v1.y;
                acc[r][1].z += pr[r] * v1.z;
                acc[r][1].w += pr[r] * v1.w;
            }
        }
        __syncthreads();
    }

    // ---- normalize + write ----
    #pragma unroll
    for (int r = 0; r < 8; ++r) {
        int i = (ti << 3) + r;
        float invl = 1.0f / l_r[r];
        float4 o0 = make_float4(acc[r][0].x * invl, acc[r][0].y * invl,
                                acc[r][0].z * invl, acc[r][0].w * invl);
        float4 o1 = make_float4(acc[r][1].x * invl, acc[r][1].y * invl,
                                acc[r][1].z * invl, acc[r][1].w * invl);
        size_t base = ((size_t)(b * TT + q0 + i)) * HH + (tj << 3);
        *(float4*)&out[base]     = o0;
        *(float4*)&out[base + 4] = o1;
    }
}

// ------------------------------------------------------------------
extern "C" void kernel_launch(void* const* d_in, const int* in_sizes, int n_in,
                              void* d_out, int out_size)
{
    const float* x  = (const float*)d_in[0];
    const float* Wk = (const float*)d_in[1];
    const float* Wq = (const float*)d_in[2];
    const float* Wv = (const float*)d_in[3];
    float* out = (float*)d_out;

    (void)in_sizes; (void)n_in; (void)out_size;

    cudaFuncSetAttribute(attn_kernel,
                         cudaFuncAttributeMaxDynamicSharedMemorySize,
                         ATTN_SMEM_BYTES);

    qkv_gemm_kernel<<<dim3(BB * TT / GBM, 3), 256>>>(x, Wk, Wq, Wv);
    attn_kernel<<<dim3(TT / BQ * BB), 128, ATTN_SMEM_BYTES>>>(out);
}

// round 3
// speedup vs baseline: 2.8707x; 1.8603x over previous
#include <cuda_runtime.h>
#include <cuda_bf16.h>
#include <cstdint>

#define BB 8
#define TT 2048
#define CC 1024
#define HH 128

// bf16 hi/lo split scratch for Q (pre-scaled), K, V
__device__ __nv_bfloat16 g_Qh[BB*TT*HH], g_Ql[BB*TT*HH];
__device__ __nv_bfloat16 g_Kh[BB*TT*HH], g_Kl[BB*TT*HH];
__device__ __nv_bfloat16 g_Vh[BB*TT*HH], g_Vl[BB*TT*HH];

// ------------------------------------------------------------------
// Stage 1: QKV projection GEMM (fp32 math, bf16 hi/lo split epilogue)
// ------------------------------------------------------------------
#define GBM 128
#define GBK 16
#define ASTR 132
#define BSTR 132

__device__ __forceinline__ void split_store4(
    __nv_bfloat16* __restrict__ oh, __nv_bfloat16* __restrict__ ol,
    int off, float a0, float a1, float a2, float a3)
{
    __nv_bfloat162 h0 = __floats2bfloat162_rn(a0, a1);
    __nv_bfloat162 h1 = __floats2bfloat162_rn(a2, a3);
    __nv_bfloat162 l0 = __floats2bfloat162_rn(a0 - __bfloat162float(h0.x),
                                              a1 - __bfloat162float(h0.y));
    __nv_bfloat162 l1 = __floats2bfloat162_rn(a2 - __bfloat162float(h1.x),
                                              a3 - __bfloat162float(h1.y));
    uint2 hv, lv;
    hv.x = *(uint32_t*)&h0; hv.y = *(uint32_t*)&h1;
    lv.x = *(uint32_t*)&l0; lv.y = *(uint32_t*)&l1;
    *(uint2*)&oh[off] = hv;
    *(uint2*)&ol[off] = lv;
}

__global__ __launch_bounds__(256) void qkv_gemm_kernel(
    const float* __restrict__ X,
    const float* __restrict__ Wk,
    const float* __restrict__ Wq,
    const float* __restrict__ Wv)
{
    const float* __restrict__ W;
    __nv_bfloat16 *oh, *ol;
    float sc = 1.0f;
    switch (blockIdx.y) {
        case 0:  W = Wk; oh = g_Kh; ol = g_Kl; break;
        case 1:  W = Wq; oh = g_Qh; ol = g_Ql; sc = 0.08838834764831845f; break;
        default: W = Wv; oh = g_Vh; ol = g_Vl; break;
    }

    __shared__ float As[GBK * ASTR];
    __shared__ float Bs[GBK * BSTR];

    const int t  = threadIdx.x;
    const int tx = t & 15;
    const int ty = t >> 4;
    const int row0 = blockIdx.x * GBM;

    float acc[8][8];
    #pragma unroll
    for (int i = 0; i < 8; ++i)
        #pragma unroll
        for (int j = 0; j < 8; ++j) acc[i][j] = 0.f;

    for (int k0 = 0; k0 < CC; k0 += GBK) {
        #pragma unroll
        for (int r = 0; r < 2; ++r) {
            int idx = t + r * 256;
            int rr  = idx >> 2;
            int kc  = (idx & 3) << 2;
            float4 v = *(const float4*)&X[(size_t)(row0 + rr) * CC + k0 + kc];
            As[(kc + 0) * ASTR + rr] = v.x;
            As[(kc + 1) * ASTR + rr] = v.y;
            As[(kc + 2) * ASTR + rr] = v.z;
            As[(kc + 3) * ASTR + rr] = v.w;
        }
        #pragma unroll
        for (int r = 0; r < 2; ++r) {
            int idx = t + r * 256;
            int rr  = idx >> 5;
            int c4  = (idx & 31) << 2;
            *(float4*)&Bs[rr * BSTR + c4] =
                *(const float4*)&W[(size_t)(k0 + rr) * HH + c4];
        }
        __syncthreads();

        #pragma unroll
        for (int kk = 0; kk < GBK; ++kk) {
            float4 a0 = *(float4*)&As[kk * ASTR + (ty << 2)];
            float4 a1 = *(float4*)&As[kk * ASTR + 64 + (ty << 2)];
            float4 b0 = *(float4*)&Bs[kk * BSTR + (tx << 2)];
            float4 b1 = *(float4*)&Bs[kk * BSTR + 64 + (tx << 2)];
            float am[8] = {a0.x, a0.y, a0.z, a0.w, a1.x, a1.y, a1.z, a1.w};
            float bn[8] = {b0.x, b0.y, b0.z, b0.w, b1.x, b1.y, b1.z, b1.w};
            #pragma unroll
            for (int mi = 0; mi < 8; ++mi)
                #pragma unroll
                for (int ni = 0; ni < 8; ++ni)
                    acc[mi][ni] += am[mi] * bn[ni];
        }
        __syncthreads();
    }

    #pragma unroll
    for (int mi = 0; mi < 8; ++mi) {
        int rr = row0 + ((mi < 4) ? ((ty << 2) + mi) : (64 + (ty << 2) + mi - 4));
        split_store4(oh, ol, rr * HH + (tx << 2),
                     acc[mi][0]*sc, acc[mi][1]*sc, acc[mi][2]*sc, acc[mi][3]*sc);
        split_store4(oh, ol, rr * HH + 64 + (tx << 2),
                     acc[mi][4]*sc, acc[mi][5]*sc, acc[mi][6]*sc, acc[mi][7]*sc);
    }
}

// ------------------------------------------------------------------
// Stage 2 (v3): flash attention on tensor cores (bf16 hi/lo x3 MMA).
// 128 threads (4 warps), BQ=64 (16 q-rows/warp), BK=64 keys/iter.
// Q frags persistent in regs; K/V hi/lo in swizzled smem via ldmatrix.
// ------------------------------------------------------------------
#define SWZ(r,c) (((r) << 8) | ((((c) ^ ((r) & 7))) << 4))

__device__ __forceinline__ void ldsm_x4(uint32_t& r0, uint32_t& r1,
                                        uint32_t& r2, uint32_t& r3, uint32_t a)
{
    asm volatile("ldmatrix.sync.aligned.m8n8.x4.shared.b16 {%0,%1,%2,%3}, [%4];"
                 : "=r"(r0), "=r"(r1), "=r"(r2), "=r"(r3) : "r"(a));
}
__device__ __forceinline__ void ldsm_x4t(uint32_t& r0, uint32_t& r1,
                                         uint32_t& r2, uint32_t& r3, uint32_t a)
{
    asm volatile("ldmatrix.sync.aligned.m8n8.x4.trans.shared.b16 {%0,%1,%2,%3}, [%4];"
                 : "=r"(r0), "=r"(r1), "=r"(r2), "=r"(r3) : "r"(a));
}
__device__ __forceinline__ void mma_bf16(float* d, const uint32_t* a,
                                         uint32_t b0, uint32_t b1)
{
    asm volatile("mma.sync.aligned.m16n8k16.row.col.f32.bf16.bf16.f32 "
                 "{%0,%1,%2,%3}, {%4,%5,%6,%7}, {%8,%9}, {%0,%1,%2,%3};"
                 : "+f"(d[0]), "+f"(d[1]), "+f"(d[2]), "+f"(d[3])
                 : "r"(a[0]), "r"(a[1]), "r"(a[2]), "r"(a[3]), "r"(b0), "r"(b1));
}
__device__ __forceinline__ void split2(float x, float y, uint32_t& h, uint32_t& l)
{
    __nv_bfloat162 hb = __floats2bfloat162_rn(x, y);
    __nv_bfloat162 lb = __floats2bfloat162_rn(x - __bfloat162float(hb.x),
                                              y - __bfloat162float(hb.y));
    h = *(uint32_t*)&hb;
    l = *(uint32_t*)&lb;
}

#define ATTN_SMEM_BYTES 65536   // 4 regions x 16KB (Kh,Kl,Vh,Vl); Q staged in K

__global__ __launch_bounds__(128) void attn_kernel(float* __restrict__ out)
{
    extern __shared__ __align__(16) unsigned char smraw[];
    const uint32_t SKH = 0, SKL = 16384, SVH = 32768, SVL = 49152;
    const int t = threadIdx.x, lane = t & 31, w = t >> 5;
    const int bid = blockIdx.x;
    const int b  = bid & 7;
    const int qt = 31 - (bid >> 3);          // global LPT order
    const int q0 = qt * 64;
    const uint32_t sb = (uint32_t)__cvta_generic_to_shared(smraw);

    // ---- stage Q tile (hi->SKH, lo->SKL), then ldmatrix to regs ----
    #pragma unroll
    for (int r = 0; r < 8; ++r) {
        int idx = t + r * 128;
        int row = idx >> 4, c = idx & 15;
        int g = (b * TT + q0 + row) * HH + c * 8;
        *(uint4*)(smraw + SKH + SWZ(row, c)) = *(const uint4*)&g_Qh[g];
        *(uint4*)(smraw + SKL + SWZ(row, c)) = *(const uint4*)&g_Ql[g];
    }
    __syncthreads();

    uint32_t qh[8][4], ql[8][4];
    {
        int tQ  = lane >> 3;
        int rA  = w * 16 + (lane & 7) + ((tQ & 1) << 3);
        int cOf = tQ >> 1;
        #pragma unroll
        for (int ks = 0; ks < 8; ++ks) {
            int c = ks * 2 + cOf;
            ldsm_x4(qh[ks][0], qh[ks][1], qh[ks][2], qh[ks][3], sb + SKH + SWZ(rA, c));
            ldsm_x4(ql[ks][0], ql[ks][1], ql[ks][2], ql[ks][3], sb + SKL + SWZ(rA, c));
        }
    }
    __syncthreads();

    float o[16][4];
    #pragma unroll
    for (int i = 0; i < 16; ++i)
        #pragma unroll
        for (int j = 0; j < 4; ++j) o[i][j] = 0.f;
    float m0 = -1e30f, m1 = -1e30f, l0 = 0.f, l1 = 0.f;

    // lane decodes for K (b-frag, non-trans) and V (b-frag, trans)
    const int tK  = lane >> 3;
    const int rB  = (lane & 7) + ((tK >> 1) << 3);
    const int cB  = tK & 1;
    const int rVo = (lane & 7) + ((tK & 1) << 3);
    const int cVo = tK >> 1;

    for (int kt = 0; kt <= qt; ++kt) {
        // ---- load K/V hi/lo tiles ----
        #pragma unroll
        for (int r = 0; r < 8; ++r) {
            int idx = t + r * 128;
            int row = idx >> 4, c = idx & 15;
            int g  = (b * TT + kt * 64 + row) * HH + c * 8;
            int sw = SWZ(row, c);
            *(uint4*)(smraw + SKH + sw) = *(const uint4*)&g_Kh[g];
            *(uint4*)(smraw + SKL + sw) = *(const uint4*)&g_Kl[g];
            *(uint4*)(smraw + SVH + sw) = *(const uint4*)&g_Vh[g];
            *(uint4*)(smraw + SVL + sw) = *(const uint4*)&g_Vl[g];
        }
        __syncthreads();

        // ---- S = Q K^T (3-way split MMA) ----
        float s[8][4];
        #pragma unroll
        for (int i = 0; i < 8; ++i)
            #pragma unroll
            for (int j = 0; j < 4; ++j) s[i][j] = 0.f;

        #pragma unroll
        for (int ks = 0; ks < 8; ++ks) {
            #pragma unroll
            for (int p = 0; p < 4; ++p) {
                int rr = p * 16 + rB;
                int cc = ks * 2 + cB;
                uint32_t bh0, bh1, bh2, bh3, bl0, bl1, bl2, bl3;
                ldsm_x4(bh0, bh1, bh2, bh3, sb + SKH + SWZ(rr, cc));
                ldsm_x4(bl0, bl1, bl2, bl3, sb + SKL + SWZ(rr, cc));
                mma_bf16(s[2*p],     qh[ks], bh0, bh1);
                mma_bf16(s[2*p],     qh[ks], bl0, bl1);
                mma_bf16(s[2*p],     ql[ks], bh0, bh1);
                mma_bf16(s[2*p + 1], qh[ks], bh2, bh3);
                mma_bf16(s[2*p + 1], qh[ks], bl2, bl3);
                mma_bf16(s[2*p + 1], ql[ks], bh2, bh3);
            }
        }

        // ---- causal mask on diagonal tile (local coords) ----
        if (kt == qt) {
            int row0 = w * 16 + (lane >> 2);
            int colb = 2 * (lane & 3);
            #pragma unroll
            for (int nf = 0; nf < 8; ++nf) {
                int cA = nf * 8 + colb;
                if (cA     > row0)     s[nf][0] = -1e30f;
                if (cA + 1 > row0)     s[nf][1] = -1e30f;
                if (cA     > row0 + 8) s[nf][2] = -1e30f;
                if (cA + 1 > row0 + 8) s[nf][3] = -1e30f;
            }
        }

        // ---- online softmax (regs + 2 shfls per reduce) ----
        float mx0 = -1e30f, mx1 = -1e30f;
        #pragma unroll
        for (int nf = 0; nf < 8; ++nf) {
            mx0 = fmaxf(mx0, fmaxf(s[nf][0], s[nf][1]));
            mx1 = fmaxf(mx1, fmaxf(s[nf][2], s[nf][3]));
        }
        mx0 = fmaxf(mx0, __shfl_xor_sync(0xffffffffu, mx0, 1));
        mx0 = fmaxf(mx0, __shfl_xor_sync(0xffffffffu, mx0, 2));
        mx1 = fmaxf(mx1, __shfl_xor_sync(0xffffffffu, mx1, 1));
        mx1 = fmaxf(mx1, __shfl_xor_sync(0xffffffffu, mx1, 2));
        float mn0 = fmaxf(m0, mx0), mn1 = fmaxf(m1, mx1);
        float a0 = __expf(m0 - mn0), a1 = __expf(m1 - mn1);
        m0 = mn0; m1 = mn1;
        float ls0 = 0.f, ls1 = 0.f;
        #pragma unroll
        for (int nf = 0; nf < 8; ++nf) {
            s[nf][0] = __expf(s[nf][0] - mn0); ls0 += s[nf][0];
            s[nf][1] = __expf(s[nf][1] - mn0); ls0 += s[nf][1];
            s[nf][2] = __expf(s[nf][2] - mn1); ls1 += s[nf][2];
            s[nf][3] = __expf(s[nf][3] - mn1); ls1 += s[nf][3];
        }
        ls0 += __shfl_xor_sync(0xffffffffu, ls0, 1);
        ls0 += __shfl_xor_sync(0xffffffffu, ls0, 2);
        ls1 += __shfl_xor_sync(0xffffffffu, ls1, 1);
        ls1 += __shfl_xor_sync(0xffffffffu, ls1, 2);
        l0 = l0 * a0 + ls0;
        l1 = l1 * a1 + ls1;

        // ---- rescale O ----
        #pragma unroll
        for (int nd = 0; nd < 16; ++nd) {
            o[nd][0] *= a0; o[nd][1] *= a0;
            o[nd][2] *= a1; o[nd][3] *= a1;
        }

        // ---- repack P (C-frag -> A-frag) with hi/lo split ----
        uint32_t ph[4][4], pl[4][4];
        #pragma unroll
        for (int kp = 0; kp < 4; ++kp) {
            int nfA = 2 * kp, nfB = 2 * kp + 1;
            split2(s[nfA][0], s[nfA][1], ph[kp][0], pl[kp][0]);
            split2(s[nfA][2], s[nfA][3], ph[kp][1], pl[kp][1]);
            split2(s[nfB][0], s[nfB][1], ph[kp][2], pl[kp][2]);
            split2(s[nfB][2], s[nfB][3], ph[kp][3], pl[kp][3]);
        }

        // ---- O += P V (3-way split MMA) ----
        #pragma unroll
        for (int kp = 0; kp < 4; ++kp) {
            #pragma unroll
            for (int np = 0; np < 8; ++np) {
                int rV = kp * 16 + rVo;
                int cV = np * 2 + cVo;
                uint32_t vh0, vh1, vh2, vh3, vl0, vl1, vl2, vl3;
                ldsm_x4t(vh0, vh1, vh2, vh3, sb + SVH + SWZ(rV, cV));
                ldsm_x4t(vl0, vl1, vl2, vl3, sb + SVL + SWZ(rV, cV));
                mma_bf16(o[2*np],     ph[kp], vh0, vh1);
                mma_bf16(o[2*np],     ph[kp], vl0, vl1);
                mma_bf16(o[2*np],     pl[kp], vh0, vh1);
                mma_bf16(o[2*np + 1], ph[kp], vh2, vh3);
                mma_bf16(o[2*np + 1], ph[kp], vl2, vl3);
                mma_bf16(o[2*np + 1], pl[kp], vh2, vh3);
            }
        }
        __syncthreads();
    }

    // ---- normalize + write ----
    {
        int grow0 = q0 + w * 16 + (lane >> 2);
        float i0 = 1.0f / l0, i1 = 1.0f / l1;
        #pragma unroll
        for (int nd = 0; nd < 16; ++nd) {
            int col = nd * 8 + 2 * (lane & 3);
            float2 v0 = make_float2(o[nd][0] * i0, o[nd][1] * i0);
            float2 v1 = make_float2(o[nd][2] * i1, o[nd][3] * i1);
            *(float2*)&out[(size_t)(b * TT + grow0) * HH + col]       = v0;
            *(float2*)&out[(size_t)(b * TT + grow0 + 8) * HH + col]   = v1;
        }
    }
}

// ------------------------------------------------------------------
extern "C" void kernel_launch(void* const* d_in, const int* in_sizes, int n_in,
                              void* d_out, int out_size)
{
    const float* x  = (const float*)d_in[0];
    const float* Wk = (const float*)d_in[1];
    const float* Wq = (const float*)d_in[2];
    const float* Wv = (const float*)d_in[3];
    float* out = (float*)d_out;

    (void)in_sizes; (void)n_in; (void)out_size;

    cudaFuncSetAttribute(attn_kernel,
                         cudaFuncAttributeMaxDynamicSharedMemorySize,
                         ATTN_SMEM_BYTES);

    qkv_gemm_kernel<<<dim3(BB * TT / GBM, 3), 256>>>(x, Wk, Wq, Wv);
    attn_kernel<<<dim3(TT / 64 * BB), 128, ATTN_SMEM_BYTES>>>(out);
}

// round 5
// speedup vs baseline: 4.6403x; 1.6165x over previous
#include <cuda_runtime.h>
#include <cuda_bf16.h>
#include <cstdint>

#define BB 8
#define TT 2048
#define CC 1024
#define HH 128

// bf16 hi/lo split scratch for Q (pre-scaled), K, V
__device__ __nv_bfloat16 g_Qh[BB*TT*HH], g_Ql[BB*TT*HH];
__device__ __nv_bfloat16 g_Kh[BB*TT*HH], g_Kl[BB*TT*HH];
__device__ __nv_bfloat16 g_Vh[BB*TT*HH], g_Vl[BB*TT*HH];
// bf16 hi/lo pre-split weights: [3][1024][128]  (0=K,1=Q,2=V)
__device__ __nv_bfloat16 g_Wh[3*CC*HH], g_Wl[3*CC*HH];

// ---------------- common MMA helpers ----------------
__device__ __forceinline__ void ldsm_x4(uint32_t& r0, uint32_t& r1,
                                        uint32_t& r2, uint32_t& r3, uint32_t a)
{
    asm volatile("ldmatrix.sync.aligned.m8n8.x4.shared.b16 {%0,%1,%2,%3}, [%4];"
                 : "=r"(r0), "=r"(r1), "=r"(r2), "=r"(r3) : "r"(a));
}
__device__ __forceinline__ void ldsm_x4t(uint32_t& r0, uint32_t& r1,
                                         uint32_t& r2, uint32_t& r3, uint32_t a)
{
    asm volatile("ldmatrix.sync.aligned.m8n8.x4.trans.shared.b16 {%0,%1,%2,%3}, [%4];"
                 : "=r"(r0), "=r"(r1), "=r"(r2), "=r"(r3) : "r"(a));
}
__device__ __forceinline__ void mma_bf16(float* d, const uint32_t* a,
                                         uint32_t b0, uint32_t b1)
{
    asm volatile("mma.sync.aligned.m16n8k16.row.col.f32.bf16.bf16.f32 "
                 "{%0,%1,%2,%3}, {%4,%5,%6,%7}, {%8,%9}, {%0,%1,%2,%3};"
                 : "+f"(d[0]), "+f"(d[1]), "+f"(d[2]), "+f"(d[3])
                 : "r"(a[0]), "r"(a[1]), "r"(a[2]), "r"(a[3]), "r"(b0), "r"(b1));
}
__device__ __forceinline__ void split2(float x, float y, uint32_t& h, uint32_t& l)
{
    __nv_bfloat162 hb = __floats2bfloat162_rn(x, y);
    __nv_bfloat162 lb = __floats2bfloat162_rn(x - __bfloat162float(hb.x),
                                              y - __bfloat162float(hb.y));
    h = *(uint32_t*)&hb;
    l = *(uint32_t*)&lb;
}

// ------------------------------------------------------------------
// Stage 0: split W into bf16 hi/lo (runs once per launch, tiny)
// ------------------------------------------------------------------
__global__ void split_w_kernel(const float* __restrict__ Wk,
                               const float* __restrict__ Wq,
                               const float* __restrict__ Wv)
{
    const float* src = (blockIdx.y == 0) ? Wk : (blockIdx.y == 1) ? Wq : Wv;
    int base = blockIdx.y * CC * HH;
    int idx = (blockIdx.x * 256 + threadIdx.x) * 4;   // 4 floats per thread
    float4 v = *(const float4*)&src[idx];
    uint32_t h0, l0, h1, l1;
    split2(v.x, v.y, h0, l0);
    split2(v.z, v.w, h1, l1);
    *(uint2*)&g_Wh[base + idx] = make_uint2(h0, h1);
    *(uint2*)&g_Wl[base + idx] = make_uint2(l0, l1);
}

// ------------------------------------------------------------------
// Stage 1 (v2): QKV projection on tensor cores, bf16 hi/lo x3.
// Block: 256 thr (8 warps), tile 128 rows x 128 cols, K-chunk 32.
// X split to hi/lo on the fly into padded smem; W pre-split.
// Warp tile 32x64: warps (mw 0..3) x (nw 0..1).
// ------------------------------------------------------------------
// padded strides (bytes): X rows 32 bf16 -> 80 B; W rows 128 bf16 -> 272 B
#define XSTRB 80
#define WSTRB 272

__global__ __launch_bounds__(256) void qkv_mma_kernel(const float* __restrict__ X)
{
    __shared__ __align__(16) unsigned char smem[2 * 128 * XSTRB + 2 * 32 * WSTRB];
    unsigned char* sXh = smem;
    unsigned char* sXl = smem + 128 * XSTRB;
    unsigned char* sWh = smem + 2 * 128 * XSTRB;
    unsigned char* sWl = sWh + 32 * WSTRB;
    const uint32_t bXh = (uint32_t)__cvta_generic_to_shared(sXh);
    const uint32_t bXl = (uint32_t)__cvta_generic_to_shared(sXl);
    const uint32_t bWh = (uint32_t)__cvta_generic_to_shared(sWh);
    const uint32_t bWl = (uint32_t)__cvta_generic_to_shared(sWl);

    const int t    = threadIdx.x;
    const int lane = t & 31;
    const int w    = t >> 5;
    const int mw   = w >> 1;          // 0..3
    const int nw   = w & 1;           // 0..1
    const int sel  = blockIdx.y;      // 0=K,1=Q,2=V
    const int row0 = blockIdx.x * 128;
    const int wbase = sel * CC * HH;

    float c[2][8][4];
    #pragma unroll
    for (int mf = 0; mf < 2; ++mf)
        #pragma unroll
        for (int nf = 0; nf < 8; ++nf)
            #pragma unroll
            for (int e = 0; e < 4; ++e) c[mf][nf][e] = 0.f;

    // lane decodes (identical pattern to attn kernel)
    const int tQ  = lane >> 3;
    const int rAo = (lane & 7) + ((tQ & 1) << 3);
    const int cAo = tQ >> 1;                       // 0..1
    const int rBo = (lane & 7) + ((tQ & 1) << 3);  // k-row within 16
    const int cBo = tQ >> 1;                       // chunk offset 0..1

    for (int k0 = 0; k0 < CC; k0 += 32) {
        // ---- stage X chunk: 128 rows x 32 floats, split to hi/lo ----
        #pragma unroll
        for (int r = 0; r < 4; ++r) {
            int idx = t + r * 256;        // 0..1023 float4s
            int row = idx >> 3;           // 0..127
            int c4  = idx & 7;            // float4 within 32 floats
            float4 v = *(const float4*)&X[(size_t)(row0 + row) * CC + k0 + c4 * 4];
            uint32_t h0, l0, h1, l1;
            split2(v.x, v.y, h0, l0);
            split2(v.z, v.w, h1, l1);
            *(uint2*)(sXh + row * XSTRB + c4 * 8) = make_uint2(h0, h1);
            *(uint2*)(sXl + row * XSTRB + c4 * 8) = make_uint2(l0, l1);
        }
        // ---- stage W chunk: 32 rows x 128 bf16 (pre-split) ----
        #pragma unroll
        for (int r = 0; r < 4; ++r) {
            int idx = t + r * 256;        // 0..1023 uint2s (4 bf16 each)
            int row = idx >> 5;           // 0..31
            int c4  = idx & 31;
            int g = wbase + (k0 + row) * HH + c4 * 4;
            *(uint2*)(sWh + row * WSTRB + c4 * 8) = *(const uint2*)&g_Wh[g];
            *(uint2*)(sWl + row * WSTRB + c4 * 8) = *(const uint2*)&g_Wl[g];
        }
        __syncthreads();

        #pragma unroll
        for (int ks = 0; ks < 2; ++ks) {
            // A frags (X): 2 m16-blocks, hi+lo
            uint32_t ah[2][4], al[2][4];
            #pragma unroll
            for (int mf = 0; mf < 2; ++mf) {
                uint32_t addr = (mw * 32 + mf * 16 + rAo) * XSTRB + (ks * 2 + cAo) * 16;
                ldsm_x4(ah[mf][0], ah[mf][1], ah[mf][2], ah[mf][3], bXh + addr);
                ldsm_x4(al[mf][0], al[mf][1], al[mf][2], al[mf][3], bXl + addr);
            }
            // B frags (W, trans): 4 n16-groups, hi+lo
            uint32_t bh[8][2], bl[8][2];
            #pragma unroll
            for (int nn = 0; nn < 4; ++nn) {
                uint32_t addr = (ks * 16 + rBo) * WSTRB + (nw * 8 + nn * 2 + cBo) * 16;
                uint32_t h0, h1, h2, h3, l0_, l1_, l2_, l3_;
                ldsm_x4t(h0, h1, h2, h3, bWh + addr);
                ldsm_x4t(l0_, l1_, l2_, l3_, bWl + addr);
                bh[nn*2][0] = h0; bh[nn*2][1] = h1;
                bh[nn*2+1][0] = h2; bh[nn*2+1][1] = h3;
                bl[nn*2][0] = l0_; bl[nn*2][1] = l1_;
                bl[nn*2+1][0] = l2_; bl[nn*2+1][1] = l3_;
            }
            // MMAs: 2m x 8n x 3 terms
            #pragma unroll
            for (int mf = 0; mf < 2; ++mf)
                #pragma unroll
                for (int nf = 0; nf < 8; ++nf) {
                    mma_bf16(c[mf][nf], ah[mf], bh[nf][0], bh[nf][1]);
                    mma_bf16(c[mf][nf], ah[mf], bl[nf][0], bl[nf][1]);
                    mma_bf16(c[mf][nf], al[mf], bh[nf][0], bh[nf][1]);
                }
        }
        __syncthreads();
    }

    // ---- epilogue: split-store to bf16 hi/lo outputs ----
    __nv_bfloat16 *oh, *ol;
    float sc = 1.0f;
    switch (sel) {
        case 0:  oh = g_Kh; ol = g_Kl; break;
        case 1:  oh = g_Qh; ol = g_Ql; sc = 0.08838834764831845f; break;
        default: oh = g_Vh; ol = g_Vl; break;
    }
    #pragma unroll
    for (int mf = 0; mf < 2; ++mf) {
        #pragma unroll
        for (int nf = 0; nf < 8; ++nf) {
            int row = row0 + mw * 32 + mf * 16 + (lane >> 2);
            int col = nw * 64 + nf * 8 + (lane & 3) * 2;
            uint32_t h, l;
            split2(c[mf][nf][0] * sc, c[mf][nf][1] * sc, h, l);
            *(uint32_t*)&oh[(size_t)row * HH + col] = h;
            *(uint32_t*)&ol[(size_t)row * HH + col] = l;
            split2(c[mf][nf][2] * sc, c[mf][nf][3] * sc, h, l);
            *(uint32_t*)&oh[(size_t)(row + 8) * HH + col] = h;
            *(uint32_t*)&ol[(size_t)(row + 8) * HH + col] = l;
        }
    }
}

// ------------------------------------------------------------------
// Stage 2: flash attention on tensor cores (bf16 hi/lo x3) — as R3.
// ------------------------------------------------------------------
#define SWZ(r,c) (((r) << 8) | ((((c) ^ ((r) & 7))) << 4))
#define ATTN_SMEM_BYTES 65536

__global__ __launch_bounds__(128) void attn_kernel(float* __restrict__ out)
{
    extern __shared__ __align__(16) unsigned char smraw[];
    const uint32_t SKH = 0, SKL = 16384, SVH = 32768, SVL = 49152;
    const int t = threadIdx.x, lane = t & 31, w = t >> 5;
    const int bid = blockIdx.x;
    const int b  = bid & 7;
    const int qt = 31 - (bid >> 3);
    const int q0 = qt * 64;
    const uint32_t sb = (uint32_t)__cvta_generic_to_shared(smraw);

    #pragma unroll
    for (int r = 0; r < 8; ++r) {
        int idx = t + r * 128;
        int row = idx >> 4, c = idx & 15;
        int g = (b * TT + q0 + row) * HH + c * 8;
        *(uint4*)(smraw + SKH + SWZ(row, c)) = *(const uint4*)&g_Qh[g];
        *(uint4*)(smraw + SKL + SWZ(row, c)) = *(const uint4*)&g_Ql[g];
    }
    __syncthreads();

    uint32_t qh[8][4], ql[8][4];
    {
        int tQ  = lane >> 3;
        int rA  = w * 16 + (lane & 7) + ((tQ & 1) << 3);
        int cOf = tQ >> 1;
        #pragma unroll
        for (int ks = 0; ks < 8; ++ks) {
            int c = ks * 2 + cOf;
            ldsm_x4(qh[ks][0], qh[ks][1], qh[ks][2], qh[ks][3], sb + SKH + SWZ(rA, c));
            ldsm_x4(ql[ks][0], ql[ks][1], ql[ks][2], ql[ks][3], sb + SKL + SWZ(rA, c));
        }
    }
    __syncthreads();

    float o[16][4];
    #pragma unroll
    for (int i = 0; i < 16; ++i)
        #pragma unroll
        for (int j = 0; j < 4; ++j) o[i][j] = 0.f;
    float m0 = -1e30f, m1 = -1e30f, l0 = 0.f, l1 = 0.f;

    const int tK  = lane >> 3;
    const int rB  = (lane & 7) + ((tK >> 1) << 3);
    const int cB  = tK & 1;
    const int rVo = (lane & 7) + ((tK & 1) << 3);
    const int cVo = tK >> 1;

    for (int kt = 0; kt <= qt; ++kt) {
        #pragma unroll
        for (int r = 0; r < 8; ++r) {
            int idx = t + r * 128;
            int row = idx >> 4, c = idx & 15;
            int g  = (b * TT + kt * 64 + row) * HH + c * 8;
            int sw = SWZ(row, c);
            *(uint4*)(smraw + SKH + sw) = *(const uint4*)&g_Kh[g];
            *(uint4*)(smraw + SKL + sw) = *(const uint4*)&g_Kl[g];
            *(uint4*)(smraw + SVH + sw) = *(const uint4*)&g_Vh[g];
            *(uint4*)(smraw + SVL + sw) = *(const uint4*)&g_Vl[g];
        }
        __syncthreads();

        float s[8][4];
        #pragma unroll
        for (int i = 0; i < 8; ++i)
            #pragma unroll
            for (int j = 0; j < 4; ++j) s[i][j] = 0.f;

        #pragma unroll
        for (int ks = 0; ks < 8; ++ks) {
            #pragma unroll
            for (int p = 0; p < 4; ++p) {
                int rr = p * 16 + rB;
                int cc = ks * 2 + cB;
                uint32_t bh0, bh1, bh2, bh3, bl0, bl1, bl2, bl3;
                ldsm_x4(bh0, bh1, bh2, bh3, sb + SKH + SWZ(rr, cc));
                ldsm_x4(bl0, bl1, bl2, bl3, sb + SKL + SWZ(rr, cc));
                mma_bf16(s[2*p],     qh[ks], bh0, bh1);
                mma_bf16(s[2*p],     qh[ks], bl0, bl1);
                mma_bf16(s[2*p],     ql[ks], bh0, bh1);
                mma_bf16(s[2*p + 1], qh[ks], bh2, bh3);
                mma_bf16(s[2*p + 1], qh[ks], bl2, bl3);
                mma_bf16(s[2*p + 1], ql[ks], bh2, bh3);
            }
        }

        if (kt == qt) {
            int row0 = w * 16 + (lane >> 2);
            int colb = 2 * (lane & 3);
            #pragma unroll
            for (int nf = 0; nf < 8; ++nf) {
                int cA = nf * 8 + colb;
                if (cA     > row0)     s[nf][0] = -1e30f;
                if (cA + 1 > row0)     s[nf][1] = -1e30f;
                if (cA     > row0 + 8) s[nf][2] = -1e30f;
                if (cA + 1 > row0 + 8) s[nf][3] = -1e30f;
            }
        }

        float mx0 = -1e30f, mx1 = -1e30f;
        #pragma unroll
        for (int nf = 0; nf < 8; ++nf) {
            mx0 = fmaxf(mx0, fmaxf(s[nf][0], s[nf][1]));
            mx1 = fmaxf(mx1, fmaxf(s[nf][2], s[nf][3]));
        }
        mx0 = fmaxf(mx0, __shfl_xor_sync(0xffffffffu, mx0, 1));
        mx0 = fmaxf(mx0, __shfl_xor_sync(0xffffffffu, mx0, 2));
        mx1 = fmaxf(mx1, __shfl_xor_sync(0xffffffffu, mx1, 1));
        mx1 = fmaxf(mx1, __shfl_xor_sync(0xffffffffu, mx1, 2));
        float mn0 = fmaxf(m0, mx0), mn1 = fmaxf(m1, mx1);
        float a0 = __expf(m0 - mn0), a1 = __expf(m1 - mn1);
        m0 = mn0; m1 = mn1;
        float ls0 = 0.f, ls1 = 0.f;
        #pragma unroll
        for (int nf = 0; nf < 8; ++nf) {
            s[nf][0] = __expf(s[nf][0] - mn0); ls0 += s[nf][0];
            s[nf][1] = __expf(s[nf][1] - mn0); ls0 += s[nf][1];
            s[nf][2] = __expf(s[nf][2] - mn1); ls1 += s[nf][2];
            s[nf][3] = __expf(s[nf][3] - mn1); ls1 += s[nf][3];
        }
        ls0 += __shfl_xor_sync(0xffffffffu, ls0, 1);
        ls0 += __shfl_xor_sync(0xffffffffu, ls0, 2);
        ls1 += __shfl_xor_sync(0xffffffffu, ls1, 1);
        ls1 += __shfl_xor_sync(0xffffffffu, ls1, 2);
        l0 = l0 * a0 + ls0;
        l1 = l1 * a1 + ls1;

        #pragma unroll
        for (int nd = 0; nd < 16; ++nd) {
            o[nd][0] *= a0; o[nd][1] *= a0;
            o[nd][2] *= a1; o[nd][3] *= a1;
        }

        uint32_t ph[4][4], pl[4][4];
        #pragma unroll
        for (int kp = 0; kp < 4; ++kp) {
            int nfA = 2 * kp, nfB = 2 * kp + 1;
            split2(s[nfA][0], s[nfA][1], ph[kp][0], pl[kp][0]);
            split2(s[nfA][2], s[nfA][3], ph[kp][1], pl[kp][1]);
            split2(s[nfB][0], s[nfB][1], ph[kp][2], pl[kp][2]);
            split2(s[nfB][2], s[nfB][3], ph[kp][3], pl[kp][3]);
        }

        #pragma unroll
        for (int kp = 0; kp < 4; ++kp) {
            #pragma unroll
            for (int np = 0; np < 8; ++np) {
                int rV = kp * 16 + rVo;
                int cV = np * 2 + cVo;
                uint32_t vh0, vh1, vh2, vh3, vl0, vl1, vl2, vl3;
                ldsm_x4t(vh0, vh1, vh2, vh3, sb + SVH + SWZ(rV, cV));
                ldsm_x4t(vl0, vl1, vl2, vl3, sb + SVL + SWZ(rV, cV));
                mma_bf16(o[2*np],     ph[kp], vh0, vh1);
                mma_bf16(o[2*np],     ph[kp], vl0, vl1);
                mma_bf16(o[2*np],     pl[kp], vh0, vh1);
                mma_bf16(o[2*np + 1], ph[kp], vh2, vh3);
                mma_bf16(o[2*np + 1], ph[kp], vl2, vl3);
                mma_bf16(o[2*np + 1], pl[kp], vh2, vh3);
            }
        }
        __syncthreads();
    }

    {
        int grow0 = q0 + w * 16 + (lane >> 2);
        float i0 = 1.0f / l0, i1 = 1.0f / l1;
        #pragma unroll
        for (int nd = 0; nd < 16; ++nd) {
            int col = nd * 8 + 2 * (lane & 3);
            float2 v0 = make_float2(o[nd][0] * i0, o[nd][1] * i0);
            float2 v1 = make_float2(o[nd][2] * i1, o[nd][3] * i1);
            *(float2*)&out[(size_t)(b * TT + grow0) * HH + col]       = v0;
            *(float2*)&out[(size_t)(b * TT + grow0 + 8) * HH + col]   = v1;
        }
    }
}

// ------------------------------------------------------------------
extern "C" void kernel_launch(void* const* d_in, const int* in_sizes, int n_in,
                              void* d_out, int out_size)
{
    const float* x  = (const float*)d_in[0];
    const float* Wk = (const float*)d_in[1];
    const float* Wq = (const float*)d_in[2];
    const float* Wv = (const float*)d_in[3];
    float* out = (float*)d_out;

    (void)in_sizes; (void)n_in; (void)out_size;

    cudaFuncSetAttribute(attn_kernel,
                         cudaFuncAttributeMaxDynamicSharedMemorySize,
                         ATTN_SMEM_BYTES);

    split_w_kernel<<<dim3(CC * HH / 4 / 256, 3), 256>>>(Wk, Wq, Wv);
    qkv_mma_kernel<<<dim3(BB * TT / 128, 3), 256>>>(x);
    attn_kernel<<<dim3(TT / 64 * BB), 128, ATTN_SMEM_BYTES>>>(out);
}

// round 7
// speedup vs baseline: 5.5159x; 1.1887x over previous
#include <cuda_runtime.h>
#include <cuda_bf16.h>
#include <cstdint>

#define BB 8
#define TT 2048
#define CC 1024
#define HH 128

// bf16 hi/lo split scratch for Q (pre-scaled), K, V
__device__ __nv_bfloat16 g_Qh[BB*TT*HH], g_Ql[BB*TT*HH];
__device__ __nv_bfloat16 g_Kh[BB*TT*HH], g_Kl[BB*TT*HH];
__device__ __nv_bfloat16 g_Vh[BB*TT*HH], g_Vl[BB*TT*HH];
// bf16 hi/lo pre-split weights: [3][1024][128]  (0=K,1=Q,2=V)
__device__ __nv_bfloat16 g_Wh[3*CC*HH], g_Wl[3*CC*HH];

// ---------------- common helpers ----------------
__device__ __forceinline__ void ldsm_x4(uint32_t& r0, uint32_t& r1,
                                        uint32_t& r2, uint32_t& r3, uint32_t a)
{
    asm volatile("ldmatrix.sync.aligned.m8n8.x4.shared.b16 {%0,%1,%2,%3}, [%4];"
                 : "=r"(r0), "=r"(r1), "=r"(r2), "=r"(r3) : "r"(a));
}
__device__ __forceinline__ void ldsm_x4t(uint32_t& r0, uint32_t& r1,
                                         uint32_t& r2, uint32_t& r3, uint32_t a)
{
    asm volatile("ldmatrix.sync.aligned.m8n8.x4.trans.shared.b16 {%0,%1,%2,%3}, [%4];"
                 : "=r"(r0), "=r"(r1), "=r"(r2), "=r"(r3) : "r"(a));
}
__device__ __forceinline__ void mma_bf16(float* d, const uint32_t* a,
                                         uint32_t b0, uint32_t b1)
{
    asm volatile("mma.sync.aligned.m16n8k16.row.col.f32.bf16.bf16.f32 "
                 "{%0,%1,%2,%3}, {%4,%5,%6,%7}, {%8,%9}, {%0,%1,%2,%3};"
                 : "+f"(d[0]), "+f"(d[1]), "+f"(d[2]), "+f"(d[3])
                 : "r"(a[0]), "r"(a[1]), "r"(a[2]), "r"(a[3]), "r"(b0), "r"(b1));
}
__device__ __forceinline__ void split2(float x, float y, uint32_t& h, uint32_t& l)
{
    __nv_bfloat162 hb = __floats2bfloat162_rn(x, y);
    __nv_bfloat162 lb = __floats2bfloat162_rn(x - __bfloat162float(hb.x),
                                              y - __bfloat162float(hb.y));
    h = *(uint32_t*)&hb;
    l = *(uint32_t*)&lb;
}
__device__ __forceinline__ void cp_async16(uint32_t dst, const void* src)
{
    asm volatile("cp.async.cg.shared.global [%0], [%1], 16;"
                 :: "r"(dst), "l"(src));
}
#define CP_COMMIT()  asm volatile("cp.async.commit_group;")
#define CP_WAIT0()   asm volatile("cp.async.wait_group 0;")

// ------------------------------------------------------------------
// Stage 0: split W into bf16 hi/lo (runs once per launch, tiny)
// ------------------------------------------------------------------
__global__ void split_w_kernel(const float* __restrict__ Wk,
                               const float* __restrict__ Wq,
                               const float* __restrict__ Wv)
{
    const float* src = (blockIdx.y == 0) ? Wk : (blockIdx.y == 1) ? Wq : Wv;
    int base = blockIdx.y * CC * HH;
    int idx = (blockIdx.x * 256 + threadIdx.x) * 4;
    float4 v = *(const float4*)&src[idx];
    uint32_t h0, l0, h1, l1;
    split2(v.x, v.y, h0, l0);
    split2(v.z, v.w, h1, l1);
    *(uint2*)&g_Wh[base + idx] = make_uint2(h0, h1);
    *(uint2*)&g_Wl[base + idx] = make_uint2(l0, l1);
}

// ------------------------------------------------------------------
// Stage 1 (v3): QKV projection, bf16 hi/lo x3, double-buffered.
// W via cp.async (pre-split in gmem); X prefetched to regs during MMA,
// split+STS into next stage. One barrier per 32-k chunk.
// ------------------------------------------------------------------
#define XSTRB 80     // 32 bf16 row padded to 80 B
#define WSTRB 272    // 128 bf16 row padded to 272 B
#define OXH 0
#define OXL (128*XSTRB)              // 10240
#define OWH (2*128*XSTRB)            // 20480
#define OWL (OWH + 32*WSTRB)         // 29184
#define QKV_STG (OWL + 32*WSTRB)     // 37888
#define QKV_SMEM (2*QKV_STG)         // 75776

__global__ __launch_bounds__(256) void qkv_mma_kernel(const float* __restrict__ X)
{
    extern __shared__ __align__(16) unsigned char dsm[];
    const uint32_t sb = (uint32_t)__cvta_generic_to_shared(dsm);

    const int t    = threadIdx.x;
    const int lane = t & 31;
    const int w    = t >> 5;
    const int mw   = w >> 1;
    const int nw   = w & 1;
    const int sel  = blockIdx.y;
    const int row0 = blockIdx.x * 128;
    const int wbase = sel * CC * HH;

    float c[2][8][4];
    #pragma unroll
    for (int mf = 0; mf < 2; ++mf)
        #pragma unroll
        for (int nf = 0; nf < 8; ++nf)
            #pragma unroll
            for (int e = 0; e < 4; ++e) c[mf][nf][e] = 0.f;

    const int tQ  = lane >> 3;
    const int rAo = (lane & 7) + ((tQ & 1) << 3);
    const int cAo = tQ >> 1;
    const int rBo = (lane & 7) + ((tQ & 1) << 3);
    const int cBo = tQ >> 1;

    // W-region cp.async mapping: 512 16B-chunks per hi/lo
    const int wrow = t >> 4;          // used with +16 offset for 2nd iter
    const int wc16 = t & 15;

    // ---- prologue: W(0) via cp.async, X(0) via LDG+split+STS ----
    #pragma unroll
    for (int r = 0; r < 2; ++r) {
        int row = wrow + r * 16;
        int g = wbase + row * HH + wc16 * 8;
        cp_async16(sb + OWH + row * WSTRB + wc16 * 16, &g_Wh[g]);
        cp_async16(sb + OWL + row * WSTRB + wc16 * 16, &g_Wl[g]);
    }
    CP_COMMIT();
    #pragma unroll
    for (int r = 0; r < 4; ++r) {
        int idx = t + r * 256;
        int row = idx >> 3, c4 = idx & 7;
        float4 v = *(const float4*)&X[(size_t)(row0 + row) * CC + c4 * 4];
        uint32_t h0, l0, h1, l1;
        split2(v.x, v.y, h0, l0);
        split2(v.z, v.w, h1, l1);
        *(uint2*)(dsm + OXH + row * XSTRB + c4 * 8) = make_uint2(h0, h1);
        *(uint2*)(dsm + OXL + row * XSTRB + c4 * 8) = make_uint2(l0, l1);
    }

    for (int k0 = 0; k0 < CC; k0 += 32) {
        const int cur = (k0 >> 5) & 1;
        const uint32_t stc = sb + cur * QKV_STG;
        unsigned char* pnx = dsm + (cur ^ 1) * QKV_STG;
        const uint32_t stn = sb + (cur ^ 1) * QKV_STG;
        const bool more = (k0 + 32) < CC;

        CP_WAIT0();
        __syncthreads();

        float4 xr[4];
        if (more) {
            #pragma unroll
            for (int r = 0; r < 2; ++r) {
                int row = wrow + r * 16;
                int g = wbase + (k0 + 32 + row) * HH + wc16 * 8;
                cp_async16(stn + OWH + row * WSTRB + wc16 * 16, &g_Wh[g]);
                cp_async16(stn + OWL + row * WSTRB + wc16 * 16, &g_Wl[g]);
            }
            CP_COMMIT();
            #pragma unroll
            for (int r = 0; r < 4; ++r) {
                int idx = t + r * 256;
                int row = idx >> 3, c4 = idx & 7;
                xr[r] = *(const float4*)&X[(size_t)(row0 + row) * CC + k0 + 32 + c4 * 4];
            }
        }

        // ---- MMA on current stage ----
        #pragma unroll
        for (int ks = 0; ks < 2; ++ks) {
            uint32_t ah[2][4], al[2][4];
            #pragma unroll
            for (int mf = 0; mf < 2; ++mf) {
                uint32_t addr = stc + (mw * 32 + mf * 16 + rAo) * XSTRB + (ks * 2 + cAo) * 16;
                ldsm_x4(ah[mf][0], ah[mf][1], ah[mf][2], ah[mf][3], addr + OXH);
                ldsm_x4(al[mf][0], al[mf][1], al[mf][2], al[mf][3], addr + OXL);
            }
            uint32_t bh[8][2], bl[8][2];
            #pragma unroll
            for (int nn = 0; nn < 4; ++nn) {
                uint32_t addr = stc + (ks * 16 + rBo) * WSTRB + (nw * 8 + nn * 2 + cBo) * 16;
                uint32_t h0, h1, h2, h3, l0_, l1_, l2_, l3_;
                ldsm_x4t(h0, h1, h2, h3, addr + OWH);
                ldsm_x4t(l0_, l1_, l2_, l3_, addr + OWL);
                bh[nn*2][0] = h0; bh[nn*2][1] = h1;
                bh[nn*2+1][0] = h2; bh[nn*2+1][1] = h3;
                bl[nn*2][0] = l0_; bl[nn*2][1] = l1_;
                bl[nn*2+1][0] = l2_; bl[nn*2+1][1] = l3_;
            }
            #pragma unroll
            for (int mf = 0; mf < 2; ++mf)
                #pragma unroll
                for (int nf = 0; nf < 8; ++nf) {
                    mma_bf16(c[mf][nf], ah[mf], bh[nf][0], bh[nf][1]);
                    mma_bf16(c[mf][nf], ah[mf], bl[nf][0], bl[nf][1]);
                    mma_bf16(c[mf][nf], al[mf], bh[nf][0], bh[nf][1]);
                }
        }

        if (more) {
            #pragma unroll
            for (int r = 0; r < 4; ++r) {
                int idx = t + r * 256;
                int row = idx >> 3, c4 = idx & 7;
                uint32_t h0, l0, h1, l1;
                split2(xr[r].x, xr[r].y, h0, l0);
                split2(xr[r].z, xr[r].w, h1, l1);
                *(uint2*)(pnx + OXH + row * XSTRB + c4 * 8) = make_uint2(h0, h1);
                *(uint2*)(pnx + OXL + row * XSTRB + c4 * 8) = make_uint2(l0, l1);
            }
        }
    }

    // ---- epilogue: split-store to bf16 hi/lo outputs ----
    __nv_bfloat16 *oh, *ol;
    float sc = 1.0f;
    switch (sel) {
        case 0:  oh = g_Kh; ol = g_Kl; break;
        case 1:  oh = g_Qh; ol = g_Ql; sc = 0.08838834764831845f; break;
        default: oh = g_Vh; ol = g_Vl; break;
    }
    #pragma unroll
    for (int mf = 0; mf < 2; ++mf) {
        #pragma unroll
        for (int nf = 0; nf < 8; ++nf) {
            int row = row0 + mw * 32 + mf * 16 + (lane >> 2);
            int col = nw * 64 + nf * 8 + (lane & 3) * 2;
            uint32_t h, l;
            split2(c[mf][nf][0] * sc, c[mf][nf][1] * sc, h, l);
            *(uint32_t*)&oh[(size_t)row * HH + col] = h;
            *(uint32_t*)&ol[(size_t)row * HH + col] = l;
            split2(c[mf][nf][2] * sc, c[mf][nf][3] * sc, h, l);
            *(uint32_t*)&oh[(size_t)(row + 8) * HH + col] = h;
            *(uint32_t*)&ol[(size_t)(row + 8) * HH + col] = l;
        }
    }
}

// ------------------------------------------------------------------
// Stage 2 (v4): flash attention, bf16 hi/lo x3, cp.async double buffer.
// Stage layout (64KB): [KH 16K | KL 16K | VH 16K | VL 16K], 2 stages.
// ------------------------------------------------------------------
#define SWZ(r,c) (((r) << 8) | ((((c) ^ ((r) & 7))) << 4))
#define AST 65536
#define ATTN_SMEM_BYTES (2*AST)

__global__ __launch_bounds__(128) void attn_kernel(float* __restrict__ out)
{
    extern __shared__ __align__(16) unsigned char smraw[];
    const int t = threadIdx.x, lane = t & 31, w = t >> 5;
    const int bid = blockIdx.x;
    const int b  = bid & 7;
    const int qt = 31 - (bid >> 3);          // global LPT order
    const int q0 = qt * 64;
    const uint32_t sb = (uint32_t)__cvta_generic_to_shared(smraw);

    // ---- prologue: issue K/V(0) into stage 0 ----
    #pragma unroll
    for (int r = 0; r < 8; ++r) {
        int idx = t + r * 128;
        int row = idx >> 4, c = idx & 15;
        int g  = (b * TT + row) * HH + c * 8;   // kt=0 -> s0=0
        int sw = SWZ(row, c);
        cp_async16(sb +         sw, &g_Kh[g]);
        cp_async16(sb + 16384 + sw, &g_Kl[g]);
        cp_async16(sb + 32768 + sw, &g_Vh[g]);
        cp_async16(sb + 49152 + sw, &g_Vl[g]);
    }
    CP_COMMIT();

    // ---- stage Q into stage-1 K region, extract frags ----
    #pragma unroll
    for (int r = 0; r < 8; ++r) {
        int idx = t + r * 128;
        int row = idx >> 4, c = idx & 15;
        int g = (b * TT + q0 + row) * HH + c * 8;
        *(uint4*)(smraw + AST +         SWZ(row, c)) = *(const uint4*)&g_Qh[g];
        *(uint4*)(smraw + AST + 16384 + SWZ(row, c)) = *(const uint4*)&g_Ql[g];
    }
    __syncthreads();

    uint32_t qh[8][4], ql[8][4];
    {
        int tQ  = lane >> 3;
        int rA  = w * 16 + (lane & 7) + ((tQ & 1) << 3);
        int cOf = tQ >> 1;
        #pragma unroll
        for (int ks = 0; ks < 8; ++ks) {
            int c = ks * 2 + cOf;
            ldsm_x4(qh[ks][0], qh[ks][1], qh[ks][2], qh[ks][3], sb + AST +         SWZ(rA, c));
            ldsm_x4(ql[ks][0], ql[ks][1], ql[ks][2], ql[ks][3], sb + AST + 16384 + SWZ(rA, c));
        }
    }

    float o[16][4];
    #pragma unroll
    for (int i = 0; i < 16; ++i)
        #pragma unroll
        for (int j = 0; j < 4; ++j) o[i][j] = 0.f;
    float m0 = -1e30f, m1 = -1e30f, l0 = 0.f, l1 = 0.f;

    const int tK  = lane >> 3;
    const int rB  = (lane & 7) + ((tK >> 1) << 3);
    const int cB  = tK & 1;
    const int rVo = (lane & 7) + ((tK & 1) << 3);
    const int cVo = tK >> 1;

    for (int kt = 0; kt <= qt; ++kt) {
        const uint32_t stc = sb + (uint32_t)(kt & 1) * AST;

        CP_WAIT0();
        __syncthreads();

        // prefetch next tile into other stage
        if (kt < qt) {
            const uint32_t stn = sb + (uint32_t)((kt + 1) & 1) * AST;
            #pragma unroll
            for (int r = 0; r < 8; ++r) {
                int idx = t + r * 128;
                int row = idx >> 4, c = idx & 15;
                int g  = (b * TT + (kt + 1) * 64 + row) * HH + c * 8;
                int sw = SWZ(row, c);
                cp_async16(stn +         sw, &g_Kh[g]);
                cp_async16(stn + 16384 + sw, &g_Kl[g]);
                cp_async16(stn + 32768 + sw, &g_Vh[g]);
                cp_async16(stn + 49152 + sw, &g_Vl[g]);
            }
            CP_COMMIT();
        }

        // ---- S = Q K^T (3-way split MMA) ----
        float s[8][4];
        #pragma unroll
        for (int i = 0; i < 8; ++i)
            #pragma unroll
            for (int j = 0; j < 4; ++j) s[i][j] = 0.f;

        #pragma unroll
        for (int ks = 0; ks < 8; ++ks) {
            #pragma unroll
            for (int p = 0; p < 4; ++p) {
                int rr = p * 16 + rB;
                int cc = ks * 2 + cB;
                uint32_t bh0, bh1, bh2, bh3, bl0, bl1, bl2, bl3;
                ldsm_x4(bh0, bh1, bh2, bh3, stc +         SWZ(rr, cc));
                ldsm_x4(bl0, bl1, bl2, bl3, stc + 16384 + SWZ(rr, cc));
                mma_bf16(s[2*p],     qh[ks], bh0, bh1);
                mma_bf16(s[2*p],     qh[ks], bl0, bl1);
                mma_bf16(s[2*p],     ql[ks], bh0, bh1);
                mma_bf16(s[2*p + 1], qh[ks], bh2, bh3);
                mma_bf16(s[2*p + 1], qh[ks], bl2, bl3);
                mma_bf16(s[2*p + 1], ql[ks], bh2, bh3);
            }
        }

        if (kt == qt) {
            int row0 = w * 16 + (lane >> 2);
            int colb = 2 * (lane & 3);
            #pragma unroll
            for (int nf = 0; nf < 8; ++nf) {
                int cA = nf * 8 + colb;
                if (cA     > row0)     s[nf][0] = -1e30f;
                if (cA + 1 > row0)     s[nf][1] = -1e30f;
                if (cA     > row0 + 8) s[nf][2] = -1e30f;
                if (cA + 1 > row0 + 8) s[nf][3] = -1e30f;
            }
        }

        // ---- online softmax in registers ----
        float mx0 = -1e30f, mx1 = -1e30f;
        #pragma unroll
        for (int nf = 0; nf < 8; ++nf) {
            mx0 = fmaxf(mx0, fmaxf(s[nf][0], s[nf][1]));
            mx1 = fmaxf(mx1, fmaxf(s[nf][2], s[nf][3]));
        }
        mx0 = fmaxf(mx0, __shfl_xor_sync(0xffffffffu, mx0, 1));
        mx0 = fmaxf(mx0, __shfl_xor_sync(0xffffffffu, mx0, 2));
        mx1 = fmaxf(mx1, __shfl_xor_sync(0xffffffffu, mx1, 1));
        mx1 = fmaxf(mx1, __shfl_xor_sync(0xffffffffu, mx1, 2));
        float mn0 = fmaxf(m0, mx0), mn1 = fmaxf(m1, mx1);
        float a0 = __expf(m0 - mn0), a1 = __expf(m1 - mn1);
        m0 = mn0; m1 = mn1;
        float ls0 = 0.f, ls1 = 0.f;
        #pragma unroll
        for (int nf = 0; nf < 8; ++nf) {
            s[nf][0] = __expf(s[nf][0] - mn0); ls0 += s[nf][0];
            s[nf][1] = __expf(s[nf][1] - mn0); ls0 += s[nf][1];
            s[nf][2] = __expf(s[nf][2] - mn1); ls1 += s[nf][2];
            s[nf][3] = __expf(s[nf][3] - mn1); ls1 += s[nf][3];
        }
        ls0 += __shfl_xor_sync(0xffffffffu, ls0, 1);
        ls0 += __shfl_xor_sync(0xffffffffu, ls0, 2);
        ls1 += __shfl_xor_sync(0xffffffffu, ls1, 1);
        ls1 += __shfl_xor_sync(0xffffffffu, ls1, 2);
        l0 = l0 * a0 + ls0;
        l1 = l1 * a1 + ls1;

        #pragma unroll
        for (int nd = 0; nd < 16; ++nd) {
            o[nd][0] *= a0; o[nd][1] *= a0;
            o[nd][2] *= a1; o[nd][3] *= a1;
        }

        // ---- repack P (C-frag -> A-frag) with hi/lo split ----
        uint32_t ph[4][4], pl[4][4];
        #pragma unroll
        for (int kp = 0; kp < 4; ++kp) {
            int nfA = 2 * kp, nfB = 2 * kp + 1;
            split2(s[nfA][0], s[nfA][1], ph[kp][0], pl[kp][0]);
            split2(s[nfA][2], s[nfA][3], ph[kp][1], pl[kp][1]);
            split2(s[nfB][0], s[nfB][1], ph[kp][2], pl[kp][2]);
            split2(s[nfB][2], s[nfB][3], ph[kp][3], pl[kp][3]);
        }

        // ---- O += P V (3-way split MMA) ----
        #pragma unroll
        for (int kp = 0; kp < 4; ++kp) {
            #pragma unroll
            for (int np = 0; np < 8; ++np) {
                int rV = kp * 16 + rVo;
                int cV = np * 2 + cVo;
                uint32_t vh0, vh1, vh2, vh3, vl0, vl1, vl2, vl3;
                ldsm_x4t(vh0, vh1, vh2, vh3, stc + 32768 + SWZ(rV, cV));
                ldsm_x4t(vl0, vl1, vl2, vl3, stc + 49152 + SWZ(rV, cV));
                mma_bf16(o[2*np],     ph[kp], vh0, vh1);
                mma_bf16(o[2*np],     ph[kp], vl0, vl1);
                mma_bf16(o[2*np],     pl[kp], vh0, vh1);
                mma_bf16(o[2*np + 1], ph[kp], vh2, vh3);
                mma_bf16(o[2*np + 1], ph[kp], vl2, vl3);
                mma_bf16(o[2*np + 1], pl[kp], vh2, vh3);
            }
        }
    }

    // ---- normalize + write ----
    {
        int grow0 = q0 + w * 16 + (lane >> 2);
        float i0 = 1.0f / l0, i1 = 1.0f / l1;
        #pragma unroll
        for (int nd = 0; nd < 16; ++nd) {
            int col = nd * 8 + 2 * (lane & 3);
            float2 v0 = make_float2(o[nd][0] * i0, o[nd][1] * i0);
            float2 v1 = make_float2(o[nd][2] * i1, o[nd][3] * i1);
            *(float2*)&out[(size_t)(b * TT + grow0) * HH + col]       = v0;
            *(float2*)&out[(size_t)(b * TT + grow0 + 8) * HH + col]   = v1;
        }
    }
}

// ------------------------------------------------------------------
extern "C" void kernel_launch(void* const* d_in, const int* in_sizes, int n_in,
                              void* d_out, int out_size)
{
    const float* x  = (const float*)d_in[0];
    const float* Wk = (const float*)d_in[1];
    const float* Wq = (const float*)d_in[2];
    const float* Wv = (const float*)d_in[3];
    float* out = (float*)d_out;

    (void)in_sizes; (void)n_in; (void)out_size;

    cudaFuncSetAttribute(qkv_mma_kernel,
                         cudaFuncAttributeMaxDynamicSharedMemorySize,
                         QKV_SMEM);
    cudaFuncSetAttribute(attn_kernel,
                         cudaFuncAttributeMaxDynamicSharedMemorySize,
                         ATTN_SMEM_BYTES);

    split_w_kernel<<<dim3(CC * HH / 4 / 256, 3), 256>>>(Wk, Wq, Wv);
    qkv_mma_kernel<<<dim3(BB * TT / 128, 3), 256, QKV_SMEM>>>(x);
    attn_kernel<<<dim3(TT / 64 * BB), 128, ATTN_SMEM_BYTES>>>(out);
}